// round 10
// baseline (speedup 1.0000x reference)
#include <cuda_runtime.h>
#include <cuda_bf16.h>

// Problem: F=128 features, N=8192 batch, D=128 d_model.
// out[f,n,d] = LayerNorm_d( x[n,f]*W[f,d] + b[f,d] ) * gamma[d] + beta[d]
//
// Algebraic fusion: for fixed f the embedding row is affine in scalar x:
//   centered = x*(W-meanW) + (b-meanb)
//   var      = A*x^2 + 2B*x + C
//   A = E[W^2]-E[W]^2,  B = E[Wb]-E[W]E[b],  C = E[b^2]-E[b]^2   (per feature)
// => no per-row reduction at runtime.
//
// R10 = R9 fused single-launch kernel (no separate precompute) + R8's
// default .wb stores (__stcs measured as a 2% DRAM regression on sm_103a).

#define F_DIM 128
#define D_DIM 128
#define N_BATCH 8192
#define EPS 1e-5f

__global__ void __launch_bounds__(256)
embed_ln_kernel(const float* __restrict__ x,
                const float* __restrict__ W,
                const float* __restrict__ b,
                const float* __restrict__ gamma,
                const float* __restrict__ beta,
                float* __restrict__ out) {
    const int f    = blockIdx.x;
    const int lane = threadIdx.x & 31;
    const int warp = threadIdx.x >> 5;

    // ---- Per-feature constants, computed redundantly per warp ----
    // Lane l holds W[f, 4l..4l+3] and b[f, 4l..4l+3].
    const float4 w4 = reinterpret_cast<const float4*>(W + f * D_DIM)[lane];
    const float4 c4 = reinterpret_cast<const float4*>(b + f * D_DIM)[lane];

    float sw  = (w4.x + w4.y) + (w4.z + w4.w);
    float sb  = (c4.x + c4.y) + (c4.z + c4.w);
    float sww = w4.x * w4.x + w4.y * w4.y + w4.z * w4.z + w4.w * w4.w;
    float swb = w4.x * c4.x + w4.y * c4.y + w4.z * c4.z + w4.w * c4.w;
    float sbb = c4.x * c4.x + c4.y * c4.y + c4.z * c4.z + c4.w * c4.w;

    #pragma unroll
    for (int o = 16; o > 0; o >>= 1) {
        sw  += __shfl_xor_sync(0xffffffffu, sw,  o);
        sb  += __shfl_xor_sync(0xffffffffu, sb,  o);
        sww += __shfl_xor_sync(0xffffffffu, sww, o);
        swb += __shfl_xor_sync(0xffffffffu, swb, o);
        sbb += __shfl_xor_sync(0xffffffffu, sbb, o);
    }

    const float inv = 1.0f / D_DIM;
    const float mW  = sw * inv;
    const float mB  = sb * inv;
    const float A   = sww * inv - mW * mW;
    const float Bm  = swb * inv - mW * mB;
    const float C   = sbb * inv - mB * mB;
    const float B2  = 2.0f * Bm;

    // Per-lane affine coefficients folded with gamma/beta.
    const float4 g4 = reinterpret_cast<const float4*>(gamma)[lane];
    const float4 bt = reinterpret_cast<const float4*>(beta)[lane];
    float4 wg, bg;
    wg.x = (w4.x - mW) * g4.x;  bg.x = (c4.x - mB) * g4.x;
    wg.y = (w4.y - mW) * g4.y;  bg.y = (c4.y - mB) * g4.y;
    wg.z = (w4.z - mW) * g4.z;  bg.z = (c4.z - mB) * g4.z;
    wg.w = (w4.w - mW) * g4.w;  bg.w = (c4.w - mB) * g4.w;

    // ---- 32 rows per warp: lane l owns row n0+l ----
    const int n0 = blockIdx.y * 256 + warp * 32;

    const float xv   = __ldg(x + (size_t)(n0 + lane) * F_DIM + f);
    const float var  = fmaf(fmaf(A, xv, B2), xv, C);
    const float rinv = rsqrtf(fmaxf(var, 0.0f) + EPS);

    float4* __restrict__ base =
        reinterpret_cast<float4*>(out + (size_t)f * N_BATCH * D_DIM) +
        (size_t)n0 * (D_DIM / 4) + lane;

    #pragma unroll
    for (int r = 0; r < 32; ++r) {
        const float xr = __shfl_sync(0xffffffffu, xv,   r);
        const float rr = __shfl_sync(0xffffffffu, rinv, r);
        float4 o;
        o.x = fmaf(rr, fmaf(xr, wg.x, bg.x), bt.x);
        o.y = fmaf(rr, fmaf(xr, wg.y, bg.y), bt.y);
        o.z = fmaf(rr, fmaf(xr, wg.z, bg.z), bt.z);
        o.w = fmaf(rr, fmaf(xr, wg.w, bg.w), bt.w);
        base[r * (D_DIM / 4)] = o;   // default .wb store (R8 path)
    }
}

extern "C" void kernel_launch(void* const* d_in, const int* in_sizes, int n_in,
                              void* d_out, int out_size) {
    const float* x     = (const float*)d_in[0];  // [8192, 128]
    const float* W     = (const float*)d_in[1];  // [128, 128]
    const float* b     = (const float*)d_in[2];  // [128, 128]
    const float* gamma = (const float*)d_in[3];  // [128]
    const float* beta  = (const float*)d_in[4];  // [128]
    float* out = (float*)d_out;                  // [128, 8192, 128]

    dim3 grid(F_DIM, N_BATCH / 256);   // (128, 32) = 4096 blocks
    embed_ln_kernel<<<grid, 256>>>(x, W, b, gamma, beta, out);
}

// round 11
// speedup vs baseline: 1.0699x; 1.0699x over previous
#include <cuda_runtime.h>
#include <cuda_bf16.h>

// Problem: F=128 features, N=8192 batch, D=128 d_model.
// out[f,n,d] = LayerNorm_d( x[n,f]*W[f,d] + b[f,d] ) * gamma[d] + beta[d]
//
// Algebraic fusion: for fixed f the embedding row is affine in scalar x:
//   centered = x*(W-meanW) + (b-meanb)
//   var      = A*x^2 + 2B*x + C
//   A = E[W^2]-E[W]^2,  B = E[Wb]-E[W]E[b],  C = E[b^2]-E[b]^2   (per feature)
// => no per-row reduction at runtime.
//
// R11: kernel is at the HBM write ceiling (~6 TB/s across all schedule
// variants). This round composes the best measured pieces:
//  - single fused launch (saves ~6us wall vs two launches)
//  - __stcs stores (won isolated A/B vs .wb: 82.2 vs 82.9us)
//  - ALL global loads batched at kernel entry (one scoreboard wait), with
//    the moment reductions overlapping the load latency.

#define F_DIM 128
#define D_DIM 128
#define N_BATCH 8192
#define EPS 1e-5f

__global__ void __launch_bounds__(256)
embed_ln_kernel(const float* __restrict__ x,
                const float* __restrict__ W,
                const float* __restrict__ b,
                const float* __restrict__ gamma,
                const float* __restrict__ beta,
                float* __restrict__ out) {
    const int f    = blockIdx.x;
    const int lane = threadIdx.x & 31;
    const int warp = threadIdx.x >> 5;
    const int n0   = blockIdx.y * 256 + warp * 32;   // this warp's 32 rows

    // ---- Batch ALL independent global loads up front (single LG wait) ----
    const float  xv = __ldg(x + (size_t)(n0 + lane) * F_DIM + f);
    const float4 w4 = reinterpret_cast<const float4*>(W + f * D_DIM)[lane];
    const float4 c4 = reinterpret_cast<const float4*>(b + f * D_DIM)[lane];
    const float4 g4 = reinterpret_cast<const float4*>(gamma)[lane];
    const float4 bt = reinterpret_cast<const float4*>(beta)[lane];

    // ---- Per-feature raw moments (redundant per warp; overlaps loads) ----
    float sw  = (w4.x + w4.y) + (w4.z + w4.w);
    float sb  = (c4.x + c4.y) + (c4.z + c4.w);
    float sww = w4.x * w4.x + w4.y * w4.y + w4.z * w4.z + w4.w * w4.w;
    float swb = w4.x * c4.x + w4.y * c4.y + w4.z * c4.z + w4.w * c4.w;
    float sbb = c4.x * c4.x + c4.y * c4.y + c4.z * c4.z + c4.w * c4.w;

    #pragma unroll
    for (int o = 16; o > 0; o >>= 1) {
        sw  += __shfl_xor_sync(0xffffffffu, sw,  o);
        sb  += __shfl_xor_sync(0xffffffffu, sb,  o);
        sww += __shfl_xor_sync(0xffffffffu, sww, o);
        swb += __shfl_xor_sync(0xffffffffu, swb, o);
        sbb += __shfl_xor_sync(0xffffffffu, sbb, o);
    }

    const float inv = 1.0f / D_DIM;
    const float mW  = sw * inv;
    const float mB  = sb * inv;
    const float A   = sww * inv - mW * mW;
    const float Bm  = swb * inv - mW * mB;
    const float C   = sbb * inv - mB * mB;

    // Lane l owns row n0+l: one rsqrt per 32 rows.
    const float var  = fmaf(fmaf(A, xv, 2.0f * Bm), xv, C);
    const float rinv = rsqrtf(fmaxf(var, 0.0f) + EPS);

    // Per-lane affine coefficients folded with gamma/beta.
    float4 wg, bg;
    wg.x = (w4.x - mW) * g4.x;  bg.x = (c4.x - mB) * g4.x;
    wg.y = (w4.y - mW) * g4.y;  bg.y = (c4.y - mB) * g4.y;
    wg.z = (w4.z - mW) * g4.z;  bg.z = (c4.z - mB) * g4.z;
    wg.w = (w4.w - mW) * g4.w;  bg.w = (c4.w - mB) * g4.w;

    float4* __restrict__ base =
        reinterpret_cast<float4*>(out + (size_t)f * N_BATCH * D_DIM) +
        (size_t)n0 * (D_DIM / 4) + lane;

    #pragma unroll
    for (int r = 0; r < 32; ++r) {
        const float xr = __shfl_sync(0xffffffffu, xv,   r);
        const float rr = __shfl_sync(0xffffffffu, rinv, r);
        float4 o;
        o.x = fmaf(rr, fmaf(xr, wg.x, bg.x), bt.x);
        o.y = fmaf(rr, fmaf(xr, wg.y, bg.y), bt.y);
        o.z = fmaf(rr, fmaf(xr, wg.z, bg.z), bt.z);
        o.w = fmaf(rr, fmaf(xr, wg.w, bg.w), bt.w);
        __stcs(base + r * (D_DIM / 4), o);   // streaming store (won its A/B)
    }
}

extern "C" void kernel_launch(void* const* d_in, const int* in_sizes, int n_in,
                              void* d_out, int out_size) {
    const float* x     = (const float*)d_in[0];  // [8192, 128]
    const float* W     = (const float*)d_in[1];  // [128, 128]
    const float* b     = (const float*)d_in[2];  // [128, 128]
    const float* gamma = (const float*)d_in[3];  // [128]
    const float* beta  = (const float*)d_in[4];  // [128]
    float* out = (float*)d_out;                  // [128, 8192, 128]

    dim3 grid(F_DIM, N_BATCH / 256);   // (128, 32) = 4096 blocks
    embed_ln_kernel<<<grid, 256>>>(x, W, b, gamma, beta, out);
}